// round 5
// baseline (speedup 1.0000x reference)
#include <cuda_runtime.h>
#include <cstdint>

// Problem constants (fixed by the dataset)
#define NN      100000      // nodes
#define NE      3200000     // edges
#define NFEAT   512
#define NHID    256
#define NCLASS  16
#define KHOPS   10

#define CB      391         // ceil(NN/256) — scan blocks

// ---------------------------------------------------------------------------
// Device scratch (no cudaMalloc allowed)
// ---------------------------------------------------------------------------
__device__ __align__(256) float g_deg[NN];               // degree -> dinv in-place
__device__ __align__(256) int   g_cnt[NN];               // in-degree (by col)
__device__ __align__(256) int   g_off[NN + 1];           // CSR offsets
__device__ __align__(256) int   g_cur[NN];               // fill cursors
__device__ __align__(256) int   g_bsum[CB];              // per-block cnt sums
__device__ __align__(256) int   g_bpre[CB];              // exclusive block prefix
__device__ __align__(256) int2  g_csr[NE];               // (src, bitcast norm)
__device__ __align__(256) float g_h1[(size_t)NN * NHID]; // relu(x@W1+b1)
__device__ __align__(256) float g_hA[NN * NCLASS];       // ping
__device__ __align__(256) float g_hB[NN * NCLASS];       // pong

// ---------------------------------------------------------------------------
// 0) zero: g_deg (float) + g_cnt (int), NN each
// ---------------------------------------------------------------------------
__global__ void zero_scratch_kernel() {
    int i = blockIdx.x * blockDim.x + threadIdx.x;
    if (i < NN / 4) {
        reinterpret_cast<float4*>(g_deg)[i] = make_float4(0.f, 0.f, 0.f, 0.f);
        reinterpret_cast<int4*>(g_cnt)[i]   = make_int4(0, 0, 0, 0);
    }
}

// ---------------------------------------------------------------------------
// 1) count: out-degree over row (float) + in-degree over col (int)
// ---------------------------------------------------------------------------
__global__ void count_kernel(const int* __restrict__ row, const int* __restrict__ col) {
    int e = blockIdx.x * blockDim.x + threadIdx.x;
    if (e < NE) {
        atomicAdd(&g_deg[row[e]], 1.0f);
        atomicAdd(&g_cnt[col[e]], 1);
    }
}

// 2) deg -> deg^{-1/2} in-place
__global__ void dinv_kernel() {
    int i = blockIdx.x * blockDim.x + threadIdx.x;
    if (i < NN) {
        float d = g_deg[i];
        g_deg[i] = (d > 0.f) ? rsqrtf(d) : 0.f;
    }
}

// ---------------------------------------------------------------------------
// 3) three-phase exclusive scan of g_cnt -> g_off (+ cursors)
// ---------------------------------------------------------------------------
// Phase A: per-block sum of 256 counts
__global__ void scanA_kernel() {
    __shared__ int warpsum[8];
    int i = blockIdx.x * 256 + threadIdx.x;
    int v = (i < NN) ? g_cnt[i] : 0;
#pragma unroll
    for (int o = 16; o > 0; o >>= 1) v += __shfl_down_sync(0xffffffffu, v, o);
    if ((threadIdx.x & 31) == 0) warpsum[threadIdx.x >> 5] = v;
    __syncthreads();
    if (threadIdx.x < 8) {
        int s = warpsum[threadIdx.x];
#pragma unroll
        for (int o = 4; o > 0; o >>= 1) s += __shfl_down_sync(0xffu, s, o);
        if (threadIdx.x == 0) g_bsum[blockIdx.x] = s;
    }
}

// Phase B: one block scans CB block sums (exclusive)
__global__ void scanB_kernel() {
    __shared__ int sh[512];
    int tid = threadIdx.x;
    int v = (tid < CB) ? g_bsum[tid] : 0;
    sh[tid] = v;
    __syncthreads();
    for (int off = 1; off < 512; off <<= 1) {
        int t = (tid >= off) ? sh[tid - off] : 0;
        __syncthreads();
        sh[tid] += t;
        __syncthreads();
    }
    if (tid < CB) g_bpre[tid] = sh[tid] - v;
    if (tid == 0) g_off[NN] = NE;
}

// Phase C: per-block local exclusive scan + global base; write offsets/cursors
__global__ void scanC_kernel() {
    __shared__ int sh[256];
    int tid = threadIdx.x;
    int i = blockIdx.x * 256 + tid;
    int v = (i < NN) ? g_cnt[i] : 0;
    sh[tid] = v;
    __syncthreads();
    for (int off = 1; off < 256; off <<= 1) {
        int t = (tid >= off) ? sh[tid - off] : 0;
        __syncthreads();
        sh[tid] += t;
        __syncthreads();
    }
    if (i < NN) {
        int excl = sh[tid] - v + g_bpre[blockIdx.x];
        g_off[i] = excl;
        g_cur[i] = excl;
    }
}

// ---------------------------------------------------------------------------
// 4) fill CSR: bucket edges by col, record (src, norm)
// ---------------------------------------------------------------------------
__global__ void fill_kernel(const int* __restrict__ row, const int* __restrict__ col) {
    int e = blockIdx.x * blockDim.x + threadIdx.x;
    if (e >= NE) return;
    int r = __ldg(&row[e]);
    int c = __ldg(&col[e]);
    float nrm = g_deg[r] * g_deg[c];            // g_deg holds dinv here
    int pos = atomicAdd(&g_cur[c], 1);
    g_csr[pos] = make_int2(r, __float_as_int(nrm));
}

// ---------------------------------------------------------------------------
// 5) GEMM1: h1 = relu(x @ W1 + b1)   [NN,512]@[512,256]
// ---------------------------------------------------------------------------
#define G1_BM 64
#define G1_BK 16
#define G1_XSP 68

__global__ void __launch_bounds__(256, 2) gemm1_kernel(
    const float* __restrict__ x, const float* __restrict__ W1,
    const float* __restrict__ b1)
{
    __shared__ float xs[G1_BK * G1_XSP];
    __shared__ float w1s[G1_BK * NHID];

    const int tid = threadIdx.x;
    const int rowBase = blockIdx.x * G1_BM;
    const int tr = tid >> 5;
    const int tc = tid & 31;

    const int lm = tid >> 2;
    const int lk = (tid & 3) * 4;
    const int xr = rowBase + lm;
    const bool xok = (xr < NN);

    int wk[4], wn[4];
#pragma unroll
    for (int i = 0; i < 4; i++) {
        int id = tid + i * 256;
        wk[i] = id >> 6;
        wn[i] = (id & 63) * 4;
    }

    float acc[8][8];
#pragma unroll
    for (int i = 0; i < 8; i++)
#pragma unroll
        for (int j = 0; j < 8; j++) acc[i][j] = 0.f;

    const float4 z4 = make_float4(0.f, 0.f, 0.f, 0.f);
    float4 fx;
    float4 fw[4];

    fx = xok ? *reinterpret_cast<const float4*>(&x[(size_t)xr * NFEAT + lk]) : z4;
#pragma unroll
    for (int i = 0; i < 4; i++)
        fw[i] = *reinterpret_cast<const float4*>(&W1[(size_t)wk[i] * NHID + wn[i]]);

    xs[(lk + 0) * G1_XSP + lm] = fx.x;
    xs[(lk + 1) * G1_XSP + lm] = fx.y;
    xs[(lk + 2) * G1_XSP + lm] = fx.z;
    xs[(lk + 3) * G1_XSP + lm] = fx.w;
#pragma unroll
    for (int i = 0; i < 4; i++)
        *reinterpret_cast<float4*>(&w1s[wk[i] * NHID + wn[i]]) = fw[i];
    __syncthreads();

    const int NSTEPS = NFEAT / G1_BK;
    for (int kb = 0; kb < NSTEPS; kb++) {
        if (kb + 1 < NSTEPS) {
            int kBase = (kb + 1) * G1_BK;
            fx = xok ? *reinterpret_cast<const float4*>(&x[(size_t)xr * NFEAT + kBase + lk]) : z4;
#pragma unroll
            for (int i = 0; i < 4; i++)
                fw[i] = *reinterpret_cast<const float4*>(&W1[(size_t)(kBase + wk[i]) * NHID + wn[i]]);
        }
#pragma unroll
        for (int k = 0; k < G1_BK; k++) {
            float a[8], b[8];
            float4 t;
            t = *reinterpret_cast<const float4*>(&xs[k * G1_XSP + tr * 8]);
            a[0] = t.x; a[1] = t.y; a[2] = t.z; a[3] = t.w;
            t = *reinterpret_cast<const float4*>(&xs[k * G1_XSP + tr * 8 + 4]);
            a[4] = t.x; a[5] = t.y; a[6] = t.z; a[7] = t.w;
            t = *reinterpret_cast<const float4*>(&w1s[k * NHID + tc * 8]);
            b[0] = t.x; b[1] = t.y; b[2] = t.z; b[3] = t.w;
            t = *reinterpret_cast<const float4*>(&w1s[k * NHID + tc * 8 + 4]);
            b[4] = t.x; b[5] = t.y; b[6] = t.z; b[7] = t.w;
#pragma unroll
            for (int i = 0; i < 8; i++)
#pragma unroll
                for (int j = 0; j < 8; j++)
                    acc[i][j] += a[i] * b[j];
        }
        if (kb + 1 < NSTEPS) {
            __syncthreads();
            xs[(lk + 0) * G1_XSP + lm] = fx.x;
            xs[(lk + 1) * G1_XSP + lm] = fx.y;
            xs[(lk + 2) * G1_XSP + lm] = fx.z;
            xs[(lk + 3) * G1_XSP + lm] = fx.w;
#pragma unroll
            for (int i = 0; i < 4; i++)
                *reinterpret_cast<float4*>(&w1s[wk[i] * NHID + wn[i]]) = fw[i];
            __syncthreads();
        }
    }

    float bv[8];
#pragma unroll
    for (int j = 0; j < 8; j++) bv[j] = b1[tc * 8 + j];

#pragma unroll
    for (int i = 0; i < 8; i++) {
        int r = rowBase + tr * 8 + i;
        if (r < NN) {
            float4 o0, o1;
            o0.x = fmaxf(acc[i][0] + bv[0], 0.f);
            o0.y = fmaxf(acc[i][1] + bv[1], 0.f);
            o0.z = fmaxf(acc[i][2] + bv[2], 0.f);
            o0.w = fmaxf(acc[i][3] + bv[3], 0.f);
            o1.x = fmaxf(acc[i][4] + bv[4], 0.f);
            o1.y = fmaxf(acc[i][5] + bv[5], 0.f);
            o1.z = fmaxf(acc[i][6] + bv[6], 0.f);
            o1.w = fmaxf(acc[i][7] + bv[7], 0.f);
            *reinterpret_cast<float4*>(&g_h1[(size_t)r * NHID + tc * 8])     = o0;
            *reinterpret_cast<float4*>(&g_h1[(size_t)r * NHID + tc * 8 + 4]) = o1;
        }
    }
}

// ---------------------------------------------------------------------------
// 6) GEMM2: h0 = h1 @ W2 + b2 -> g_hA; also out = gamma[0]*h0
// ---------------------------------------------------------------------------
__global__ void gemm2_kernel(const float* __restrict__ W2, const float* __restrict__ b2,
                             const float* __restrict__ gamma, float* __restrict__ out)
{
    __shared__ float4 w2s[NHID * 4];
    const int tid = threadIdx.x;
#pragma unroll
    for (int i = 0; i < 4; i++) {
        int j = tid + i * 256;
        w2s[j] = reinterpret_cast<const float4*>(W2)[j];
    }
    __syncthreads();

    const int row = blockIdx.x * 256 + tid;
    if (row >= NN) return;

    float4 acc[4];
#pragma unroll
    for (int g = 0; g < 4; g++) acc[g] = reinterpret_cast<const float4*>(b2)[g];

    const float4* hr = reinterpret_cast<const float4*>(g_h1 + (size_t)row * NHID);
#pragma unroll 8
    for (int k4 = 0; k4 < NHID / 4; k4++) {
        float4 v = hr[k4];
        float s[4] = {v.x, v.y, v.z, v.w};
#pragma unroll
        for (int u = 0; u < 4; u++) {
#pragma unroll
            for (int g = 0; g < 4; g++) {
                float4 w = w2s[(k4 * 4 + u) * 4 + g];
                acc[g].x += s[u] * w.x;
                acc[g].y += s[u] * w.y;
                acc[g].z += s[u] * w.z;
                acc[g].w += s[u] * w.w;
            }
        }
    }

    float g0 = __ldg(&gamma[0]);
    float4* ha = reinterpret_cast<float4*>(g_hA) + row * 4;
    float4* op = reinterpret_cast<float4*>(out) + row * 4;
#pragma unroll
    for (int g = 0; g < 4; g++) {
        ha[g] = acc[g];
        float4 o;
        o.x = g0 * acc[g].x; o.y = g0 * acc[g].y;
        o.z = g0 * acc[g].z; o.w = g0 * acc[g].w;
        op[g] = o;
    }
}

// ---------------------------------------------------------------------------
// 7) gather sweep: one thread per node, all 16 classes.
//    h_new[n] = sum_{e in CSR[n]} norm_e * h[src_e]; fused out += gamma[k]*h_new
// ---------------------------------------------------------------------------
__global__ void __launch_bounds__(256) gather_kernel(
    float* __restrict__ out, const float* __restrict__ gamma, int k, int flip)
{
    int n = blockIdx.x * blockDim.x + threadIdx.x;
    if (n >= NN) return;

    const float4* src = reinterpret_cast<const float4*>(flip ? g_hB : g_hA);
    float4*       dst = reinterpret_cast<float4*>(flip ? g_hA : g_hB);

    int e0 = __ldg(&g_off[n]);
    int e1 = __ldg(&g_off[n + 1]);

    float4 a0 = make_float4(0.f, 0.f, 0.f, 0.f);
    float4 a1 = a0, a2 = a0, a3 = a0;

#pragma unroll 2
    for (int e = e0; e < e1; e++) {
        int2 er = __ldg(&g_csr[e]);
        float w = __int_as_float(er.y);
        const float4* s = src + er.x * 4;
        float4 v0 = __ldg(s + 0);
        float4 v1 = __ldg(s + 1);
        float4 v2 = __ldg(s + 2);
        float4 v3 = __ldg(s + 3);
        a0.x += w * v0.x; a0.y += w * v0.y; a0.z += w * v0.z; a0.w += w * v0.w;
        a1.x += w * v1.x; a1.y += w * v1.y; a1.z += w * v1.z; a1.w += w * v1.w;
        a2.x += w * v2.x; a2.y += w * v2.y; a2.z += w * v2.z; a2.w += w * v2.w;
        a3.x += w * v3.x; a3.y += w * v3.y; a3.z += w * v3.z; a3.w += w * v3.w;
    }

    float4* dn = dst + n * 4;
    dn[0] = a0; dn[1] = a1; dn[2] = a2; dn[3] = a3;

    float g = __ldg(&gamma[k]);
    float4* op = reinterpret_cast<float4*>(out) + n * 4;
    float4 o0 = op[0], o1 = op[1], o2 = op[2], o3 = op[3];
    o0.x += g * a0.x; o0.y += g * a0.y; o0.z += g * a0.z; o0.w += g * a0.w;
    o1.x += g * a1.x; o1.y += g * a1.y; o1.z += g * a1.z; o1.w += g * a1.w;
    o2.x += g * a2.x; o2.y += g * a2.y; o2.z += g * a2.z; o2.w += g * a2.w;
    o3.x += g * a3.x; o3.y += g * a3.y; o3.z += g * a3.z; o3.w += g * a3.w;
    op[0] = o0; op[1] = o1; op[2] = o2; op[3] = o3;
}

// ---------------------------------------------------------------------------
// Launch
// ---------------------------------------------------------------------------
extern "C" void kernel_launch(void* const* d_in, const int* in_sizes, int n_in,
                              void* d_out, int out_size)
{
    const float* x     = (const float*)d_in[0];
    const int*   ei    = (const int*)  d_in[1];
    const float* W1    = (const float*)d_in[2];
    const float* b1    = (const float*)d_in[3];
    const float* W2    = (const float*)d_in[4];
    const float* b2    = (const float*)d_in[5];
    const float* gamma = (const float*)d_in[6];
    float*       out   = (float*)d_out;

    const int* row = ei;         // edge_index[0]
    const int* col = ei + NE;    // edge_index[1]

    const int TPB = 256;
    const int ZB  = (NN / 4 + TPB - 1) / TPB;
    const int EB  = (NE + TPB - 1) / TPB;        // 12500
    const int NB  = (NN + TPB - 1) / TPB;        // 391
    const int G1B = (NN + G1_BM - 1) / G1_BM;    // 1563

    zero_scratch_kernel<<<ZB, TPB>>>();
    count_kernel<<<EB, TPB>>>(row, col);
    dinv_kernel<<<NB, TPB>>>();
    scanA_kernel<<<CB, TPB>>>();
    scanB_kernel<<<1, 512>>>();
    scanC_kernel<<<CB, TPB>>>();
    fill_kernel<<<EB, TPB>>>(row, col);
    gemm1_kernel<<<G1B, TPB>>>(x, W1, b1);
    gemm2_kernel<<<NB, TPB>>>(W2, b2, gamma, out);

    for (int k = 1; k <= KHOPS; k++) {
        int flip = (k - 1) & 1;
        gather_kernel<<<NB, TPB>>>(out, gamma, k, flip);
    }
}

// round 6
// speedup vs baseline: 1.2948x; 1.2948x over previous
#include <cuda_runtime.h>
#include <cstdint>

// Problem constants (fixed by the dataset)
#define NN      100000      // nodes
#define NE      3200000     // edges
#define NFEAT   512
#define NHID    256
#define NCLASS  16
#define KHOPS   10

#define CB      391         // ceil(NN/256) — scan blocks

// ---------------------------------------------------------------------------
// Device scratch (no cudaMalloc allowed)
// ---------------------------------------------------------------------------
__device__ __align__(256) float g_deg[NN];               // degree -> dinv in-place
__device__ __align__(256) int   g_cnt[NN];               // in-degree (by col)
__device__ __align__(256) int   g_off[NN + 1];           // CSR offsets
__device__ __align__(256) int   g_cur[NN];               // fill cursors
__device__ __align__(256) int   g_bsum[CB];              // per-block cnt sums
__device__ __align__(256) int   g_bpre[CB];              // exclusive block prefix
__device__ __align__(256) int2  g_csr[NE];               // (src, bitcast norm)
__device__ __align__(256) float g_h1[(size_t)NN * NHID]; // relu(x@W1+b1)
__device__ __align__(256) float g_hA[NN * NCLASS];       // ping
__device__ __align__(256) float g_hB[NN * NCLASS];       // pong

// ---------------------------------------------------------------------------
// 0) zero: g_deg (float) + g_cnt (int), NN each
// ---------------------------------------------------------------------------
__global__ void zero_scratch_kernel() {
    int i = blockIdx.x * blockDim.x + threadIdx.x;
    if (i < NN / 4) {
        reinterpret_cast<float4*>(g_deg)[i] = make_float4(0.f, 0.f, 0.f, 0.f);
        reinterpret_cast<int4*>(g_cnt)[i]   = make_int4(0, 0, 0, 0);
    }
}

// ---------------------------------------------------------------------------
// 1) count: out-degree over row (float) + in-degree over col (int)
// ---------------------------------------------------------------------------
__global__ void count_kernel(const int* __restrict__ row, const int* __restrict__ col) {
    int e = blockIdx.x * blockDim.x + threadIdx.x;
    if (e < NE) {
        atomicAdd(&g_deg[row[e]], 1.0f);
        atomicAdd(&g_cnt[col[e]], 1);
    }
}

// 2) deg -> deg^{-1/2} in-place
__global__ void dinv_kernel() {
    int i = blockIdx.x * blockDim.x + threadIdx.x;
    if (i < NN) {
        float d = g_deg[i];
        g_deg[i] = (d > 0.f) ? rsqrtf(d) : 0.f;
    }
}

// ---------------------------------------------------------------------------
// 3) three-phase exclusive scan of g_cnt -> g_off (+ cursors)
// ---------------------------------------------------------------------------
__global__ void scanA_kernel() {
    __shared__ int warpsum[8];
    int i = blockIdx.x * 256 + threadIdx.x;
    int v = (i < NN) ? g_cnt[i] : 0;
#pragma unroll
    for (int o = 16; o > 0; o >>= 1) v += __shfl_down_sync(0xffffffffu, v, o);
    if ((threadIdx.x & 31) == 0) warpsum[threadIdx.x >> 5] = v;
    __syncthreads();
    if (threadIdx.x < 8) {
        int s = warpsum[threadIdx.x];
#pragma unroll
        for (int o = 4; o > 0; o >>= 1) s += __shfl_down_sync(0xffu, s, o);
        if (threadIdx.x == 0) g_bsum[blockIdx.x] = s;
    }
}

__global__ void scanB_kernel() {
    __shared__ int sh[512];
    int tid = threadIdx.x;
    int v = (tid < CB) ? g_bsum[tid] : 0;
    sh[tid] = v;
    __syncthreads();
    for (int off = 1; off < 512; off <<= 1) {
        int t = (tid >= off) ? sh[tid - off] : 0;
        __syncthreads();
        sh[tid] += t;
        __syncthreads();
    }
    if (tid < CB) g_bpre[tid] = sh[tid] - v;
    if (tid == 0) g_off[NN] = NE;
}

__global__ void scanC_kernel() {
    __shared__ int sh[256];
    int tid = threadIdx.x;
    int i = blockIdx.x * 256 + tid;
    int v = (i < NN) ? g_cnt[i] : 0;
    sh[tid] = v;
    __syncthreads();
    for (int off = 1; off < 256; off <<= 1) {
        int t = (tid >= off) ? sh[tid - off] : 0;
        __syncthreads();
        sh[tid] += t;
        __syncthreads();
    }
    if (i < NN) {
        int excl = sh[tid] - v + g_bpre[blockIdx.x];
        g_off[i] = excl;
        g_cur[i] = excl;
    }
}

// ---------------------------------------------------------------------------
// 4) fill CSR: bucket edges by col, record (src, norm)
// ---------------------------------------------------------------------------
__global__ void fill_kernel(const int* __restrict__ row, const int* __restrict__ col) {
    int e = blockIdx.x * blockDim.x + threadIdx.x;
    if (e >= NE) return;
    int r = __ldg(&row[e]);
    int c = __ldg(&col[e]);
    float nrm = g_deg[r] * g_deg[c];            // g_deg holds dinv here
    int pos = atomicAdd(&g_cur[c], 1);
    g_csr[pos] = make_int2(r, __float_as_int(nrm));
}

// ---------------------------------------------------------------------------
// 5) GEMM1: h1 = relu(x @ W1 + b1)   [NN,512]@[512,256]
// ---------------------------------------------------------------------------
#define G1_BM 64
#define G1_BK 16
#define G1_XSP 68

__global__ void __launch_bounds__(256, 2) gemm1_kernel(
    const float* __restrict__ x, const float* __restrict__ W1,
    const float* __restrict__ b1)
{
    __shared__ float xs[G1_BK * G1_XSP];
    __shared__ float w1s[G1_BK * NHID];

    const int tid = threadIdx.x;
    const int rowBase = blockIdx.x * G1_BM;
    const int tr = tid >> 5;
    const int tc = tid & 31;

    const int lm = tid >> 2;
    const int lk = (tid & 3) * 4;
    const int xr = rowBase + lm;
    const bool xok = (xr < NN);

    int wk[4], wn[4];
#pragma unroll
    for (int i = 0; i < 4; i++) {
        int id = tid + i * 256;
        wk[i] = id >> 6;
        wn[i] = (id & 63) * 4;
    }

    float acc[8][8];
#pragma unroll
    for (int i = 0; i < 8; i++)
#pragma unroll
        for (int j = 0; j < 8; j++) acc[i][j] = 0.f;

    const float4 z4 = make_float4(0.f, 0.f, 0.f, 0.f);
    float4 fx;
    float4 fw[4];

    fx = xok ? *reinterpret_cast<const float4*>(&x[(size_t)xr * NFEAT + lk]) : z4;
#pragma unroll
    for (int i = 0; i < 4; i++)
        fw[i] = *reinterpret_cast<const float4*>(&W1[(size_t)wk[i] * NHID + wn[i]]);

    xs[(lk + 0) * G1_XSP + lm] = fx.x;
    xs[(lk + 1) * G1_XSP + lm] = fx.y;
    xs[(lk + 2) * G1_XSP + lm] = fx.z;
    xs[(lk + 3) * G1_XSP + lm] = fx.w;
#pragma unroll
    for (int i = 0; i < 4; i++)
        *reinterpret_cast<float4*>(&w1s[wk[i] * NHID + wn[i]]) = fw[i];
    __syncthreads();

    const int NSTEPS = NFEAT / G1_BK;
    for (int kb = 0; kb < NSTEPS; kb++) {
        if (kb + 1 < NSTEPS) {
            int kBase = (kb + 1) * G1_BK;
            fx = xok ? *reinterpret_cast<const float4*>(&x[(size_t)xr * NFEAT + kBase + lk]) : z4;
#pragma unroll
            for (int i = 0; i < 4; i++)
                fw[i] = *reinterpret_cast<const float4*>(&W1[(size_t)(kBase + wk[i]) * NHID + wn[i]]);
        }
#pragma unroll
        for (int k = 0; k < G1_BK; k++) {
            float a[8], b[8];
            float4 t;
            t = *reinterpret_cast<const float4*>(&xs[k * G1_XSP + tr * 8]);
            a[0] = t.x; a[1] = t.y; a[2] = t.z; a[3] = t.w;
            t = *reinterpret_cast<const float4*>(&xs[k * G1_XSP + tr * 8 + 4]);
            a[4] = t.x; a[5] = t.y; a[6] = t.z; a[7] = t.w;
            t = *reinterpret_cast<const float4*>(&w1s[k * NHID + tc * 8]);
            b[0] = t.x; b[1] = t.y; b[2] = t.z; b[3] = t.w;
            t = *reinterpret_cast<const float4*>(&w1s[k * NHID + tc * 8 + 4]);
            b[4] = t.x; b[5] = t.y; b[6] = t.z; b[7] = t.w;
#pragma unroll
            for (int i = 0; i < 8; i++)
#pragma unroll
                for (int j = 0; j < 8; j++)
                    acc[i][j] += a[i] * b[j];
        }
        if (kb + 1 < NSTEPS) {
            __syncthreads();
            xs[(lk + 0) * G1_XSP + lm] = fx.x;
            xs[(lk + 1) * G1_XSP + lm] = fx.y;
            xs[(lk + 2) * G1_XSP + lm] = fx.z;
            xs[(lk + 3) * G1_XSP + lm] = fx.w;
#pragma unroll
            for (int i = 0; i < 4; i++)
                *reinterpret_cast<float4*>(&w1s[wk[i] * NHID + wn[i]]) = fw[i];
            __syncthreads();
        }
    }

    float bv[8];
#pragma unroll
    for (int j = 0; j < 8; j++) bv[j] = b1[tc * 8 + j];

#pragma unroll
    for (int i = 0; i < 8; i++) {
        int r = rowBase + tr * 8 + i;
        if (r < NN) {
            float4 o0, o1;
            o0.x = fmaxf(acc[i][0] + bv[0], 0.f);
            o0.y = fmaxf(acc[i][1] + bv[1], 0.f);
            o0.z = fmaxf(acc[i][2] + bv[2], 0.f);
            o0.w = fmaxf(acc[i][3] + bv[3], 0.f);
            o1.x = fmaxf(acc[i][4] + bv[4], 0.f);
            o1.y = fmaxf(acc[i][5] + bv[5], 0.f);
            o1.z = fmaxf(acc[i][6] + bv[6], 0.f);
            o1.w = fmaxf(acc[i][7] + bv[7], 0.f);
            *reinterpret_cast<float4*>(&g_h1[(size_t)r * NHID + tc * 8])     = o0;
            *reinterpret_cast<float4*>(&g_h1[(size_t)r * NHID + tc * 8 + 4]) = o1;
        }
    }
}

// ---------------------------------------------------------------------------
// 6) GEMM2: h0 = h1 @ W2 + b2 -> g_hA; also out = gamma[0]*h0
// ---------------------------------------------------------------------------
__global__ void gemm2_kernel(const float* __restrict__ W2, const float* __restrict__ b2,
                             const float* __restrict__ gamma, float* __restrict__ out)
{
    __shared__ float4 w2s[NHID * 4];
    const int tid = threadIdx.x;
#pragma unroll
    for (int i = 0; i < 4; i++) {
        int j = tid + i * 256;
        w2s[j] = reinterpret_cast<const float4*>(W2)[j];
    }
    __syncthreads();

    const int row = blockIdx.x * 256 + tid;
    if (row >= NN) return;

    float4 acc[4];
#pragma unroll
    for (int g = 0; g < 4; g++) acc[g] = reinterpret_cast<const float4*>(b2)[g];

    const float4* hr = reinterpret_cast<const float4*>(g_h1 + (size_t)row * NHID);
#pragma unroll 8
    for (int k4 = 0; k4 < NHID / 4; k4++) {
        float4 v = hr[k4];
        float s[4] = {v.x, v.y, v.z, v.w};
#pragma unroll
        for (int u = 0; u < 4; u++) {
#pragma unroll
            for (int g = 0; g < 4; g++) {
                float4 w = w2s[(k4 * 4 + u) * 4 + g];
                acc[g].x += s[u] * w.x;
                acc[g].y += s[u] * w.y;
                acc[g].z += s[u] * w.z;
                acc[g].w += s[u] * w.w;
            }
        }
    }

    float g0 = __ldg(&gamma[0]);
    float4* ha = reinterpret_cast<float4*>(g_hA) + row * 4;
    float4* op = reinterpret_cast<float4*>(out) + row * 4;
#pragma unroll
    for (int g = 0; g < 4; g++) {
        ha[g] = acc[g];
        float4 o;
        o.x = g0 * acc[g].x; o.y = g0 * acc[g].y;
        o.z = g0 * acc[g].z; o.w = g0 * acc[g].w;
        op[g] = o;
    }
}

// ---------------------------------------------------------------------------
// 7) gather sweep (round-4 form): 4 threads per node, one float4 chunk each.
//    h_new[n] = sum_{e in CSR[n]} norm_e * h[src_e]; fused out += gamma[k]*h_new
// ---------------------------------------------------------------------------
__global__ void __launch_bounds__(256) gather_kernel(
    float* __restrict__ out, const float* __restrict__ gamma, int k, int flip)
{
    int t = blockIdx.x * blockDim.x + threadIdx.x;
    if (t >= NN * 4) return;
    int n = t >> 2;
    int c = t & 3;

    const float4* src = reinterpret_cast<const float4*>(flip ? g_hB : g_hA);
    float4*       dst = reinterpret_cast<float4*>(flip ? g_hA : g_hB);

    int e0 = __ldg(&g_off[n]);
    int e1 = __ldg(&g_off[n + 1]);

    float4 acc = make_float4(0.f, 0.f, 0.f, 0.f);
#pragma unroll 4
    for (int e = e0; e < e1; e++) {
        int2 er = __ldg(&g_csr[e]);
        float w = __int_as_float(er.y);
        float4 v = __ldg(&src[er.x * 4 + c]);
        acc.x += w * v.x;
        acc.y += w * v.y;
        acc.z += w * v.z;
        acc.w += w * v.w;
    }
    dst[n * 4 + c] = acc;

    float g = __ldg(&gamma[k]);
    float4* op = reinterpret_cast<float4*>(out) + n * 4 + c;
    float4 o = *op;
    o.x += g * acc.x; o.y += g * acc.y;
    o.z += g * acc.z; o.w += g * acc.w;
    *op = o;
}

// ---------------------------------------------------------------------------
// Launch
// ---------------------------------------------------------------------------
extern "C" void kernel_launch(void* const* d_in, const int* in_sizes, int n_in,
                              void* d_out, int out_size)
{
    const float* x     = (const float*)d_in[0];
    const int*   ei    = (const int*)  d_in[1];
    const float* W1    = (const float*)d_in[2];
    const float* b1    = (const float*)d_in[3];
    const float* W2    = (const float*)d_in[4];
    const float* b2    = (const float*)d_in[5];
    const float* gamma = (const float*)d_in[6];
    float*       out   = (float*)d_out;

    const int* row = ei;         // edge_index[0]
    const int* col = ei + NE;    // edge_index[1]

    const int TPB = 256;
    const int ZB  = (NN / 4 + TPB - 1) / TPB;
    const int EB  = (NE + TPB - 1) / TPB;        // 12500
    const int NB  = (NN + TPB - 1) / TPB;        // 391
    const int GB  = (NN * 4 + TPB - 1) / TPB;    // 1563
    const int G1B = (NN + G1_BM - 1) / G1_BM;    // 1563

    zero_scratch_kernel<<<ZB, TPB>>>();
    count_kernel<<<EB, TPB>>>(row, col);
    dinv_kernel<<<NB, TPB>>>();
    scanA_kernel<<<CB, TPB>>>();
    scanB_kernel<<<1, 512>>>();
    scanC_kernel<<<CB, TPB>>>();
    fill_kernel<<<EB, TPB>>>(row, col);
    gemm1_kernel<<<G1B, TPB>>>(x, W1, b1);
    gemm2_kernel<<<NB, TPB>>>(W2, b2, gamma, out);

    for (int k = 1; k <= KHOPS; k++) {
        int flip = (k - 1) & 1;
        gather_kernel<<<GB, TPB>>>(out, gamma, k, flip);
    }
}

// round 7
// speedup vs baseline: 1.7060x; 1.3176x over previous
#include <cuda_runtime.h>
#include <cuda_bf16.h>
#include <cstdint>

// Problem constants (fixed by the dataset)
#define NN      100000      // nodes
#define NE      3200000     // edges
#define NFEAT   512
#define NHID    256
#define NCLASS  16
#define KHOPS   10

#define CB      391         // ceil(NN/256) — scan blocks

// ---------------------------------------------------------------------------
// Device scratch (no cudaMalloc allowed)
// ---------------------------------------------------------------------------
__device__ __align__(256) float g_deg[NN];               // degree -> dinv in-place
__device__ __align__(256) int   g_cnt[NN];               // in-degree (by col)
__device__ __align__(256) int   g_off[NN + 1];           // CSR offsets
__device__ __align__(256) int   g_cur[NN];               // fill cursors
__device__ __align__(256) int   g_bsum[CB];              // per-block cnt sums
__device__ __align__(256) int   g_bpre[CB];              // exclusive block prefix
__device__ __align__(256) int2  g_csr[NE];               // (src, bitcast norm)
__device__ __align__(256) float g_h1[(size_t)NN * NHID]; // relu(x@W1+b1)
__device__ __align__(256) float g_hA[NN * NCLASS];       // ping
__device__ __align__(256) float g_hB[NN * NCLASS];       // pong

// bf16 split operands for tensor-core GEMM1
__device__ __align__(256) __nv_bfloat16 g_xhi[(size_t)NN * NFEAT];
__device__ __align__(256) __nv_bfloat16 g_xlo[(size_t)NN * NFEAT];
__device__ __align__(256) __nv_bfloat16 g_w1hi[NHID * NFEAT];  // W1^T [n][k]
__device__ __align__(256) __nv_bfloat16 g_w1lo[NHID * NFEAT];

// ---------------------------------------------------------------------------
// helpers
// ---------------------------------------------------------------------------
__device__ __forceinline__ uint32_t smem_u32(const void* p) {
    uint32_t a;
    asm("{ .reg .u64 t; cvta.to.shared.u64 t, %1; cvt.u32.u64 %0, t; }"
        : "=r"(a) : "l"(p));
    return a;
}
__device__ __forceinline__ void cpa16(uint32_t d, const void* s) {
    asm volatile("cp.async.cg.shared.global [%0], [%1], 16;" :: "r"(d), "l"(s));
}
__device__ __forceinline__ void mma_bf16(float* d, const uint32_t* a, const uint32_t* b) {
    asm volatile("mma.sync.aligned.m16n8k16.row.col.f32.bf16.bf16.f32 "
                 "{%0,%1,%2,%3}, {%4,%5,%6,%7}, {%8,%9}, {%0,%1,%2,%3};"
                 : "+f"(d[0]), "+f"(d[1]), "+f"(d[2]), "+f"(d[3])
                 : "r"(a[0]), "r"(a[1]), "r"(a[2]), "r"(a[3]),
                   "r"(b[0]), "r"(b[1]));
}

// ---------------------------------------------------------------------------
// 0) zero: g_deg (float) + g_cnt (int), NN each
// ---------------------------------------------------------------------------
__global__ void zero_scratch_kernel() {
    int i = blockIdx.x * blockDim.x + threadIdx.x;
    if (i < NN / 4) {
        reinterpret_cast<float4*>(g_deg)[i] = make_float4(0.f, 0.f, 0.f, 0.f);
        reinterpret_cast<int4*>(g_cnt)[i]   = make_int4(0, 0, 0, 0);
    }
}

// ---------------------------------------------------------------------------
// 1) count: out-degree over row (float) + in-degree over col (int)
// ---------------------------------------------------------------------------
__global__ void count_kernel(const int* __restrict__ row, const int* __restrict__ col) {
    int e = blockIdx.x * blockDim.x + threadIdx.x;
    if (e < NE) {
        atomicAdd(&g_deg[row[e]], 1.0f);
        atomicAdd(&g_cnt[col[e]], 1);
    }
}

// 2) deg -> deg^{-1/2} in-place
__global__ void dinv_kernel() {
    int i = blockIdx.x * blockDim.x + threadIdx.x;
    if (i < NN) {
        float d = g_deg[i];
        g_deg[i] = (d > 0.f) ? rsqrtf(d) : 0.f;
    }
}

// ---------------------------------------------------------------------------
// 3) three-phase exclusive scan of g_cnt -> g_off (+ cursors)
// ---------------------------------------------------------------------------
__global__ void scanA_kernel() {
    __shared__ int warpsum[8];
    int i = blockIdx.x * 256 + threadIdx.x;
    int v = (i < NN) ? g_cnt[i] : 0;
#pragma unroll
    for (int o = 16; o > 0; o >>= 1) v += __shfl_down_sync(0xffffffffu, v, o);
    if ((threadIdx.x & 31) == 0) warpsum[threadIdx.x >> 5] = v;
    __syncthreads();
    if (threadIdx.x < 8) {
        int s = warpsum[threadIdx.x];
#pragma unroll
        for (int o = 4; o > 0; o >>= 1) s += __shfl_down_sync(0xffu, s, o);
        if (threadIdx.x == 0) g_bsum[blockIdx.x] = s;
    }
}

__global__ void scanB_kernel() {
    __shared__ int sh[512];
    int tid = threadIdx.x;
    int v = (tid < CB) ? g_bsum[tid] : 0;
    sh[tid] = v;
    __syncthreads();
    for (int off = 1; off < 512; off <<= 1) {
        int t = (tid >= off) ? sh[tid - off] : 0;
        __syncthreads();
        sh[tid] += t;
        __syncthreads();
    }
    if (tid < CB) g_bpre[tid] = sh[tid] - v;
    if (tid == 0) g_off[NN] = NE;
}

__global__ void scanC_kernel() {
    __shared__ int sh[256];
    int tid = threadIdx.x;
    int i = blockIdx.x * 256 + tid;
    int v = (i < NN) ? g_cnt[i] : 0;
    sh[tid] = v;
    __syncthreads();
    for (int off = 1; off < 256; off <<= 1) {
        int t = (tid >= off) ? sh[tid - off] : 0;
        __syncthreads();
        sh[tid] += t;
        __syncthreads();
    }
    if (i < NN) {
        int excl = sh[tid] - v + g_bpre[blockIdx.x];
        g_off[i] = excl;
        g_cur[i] = excl;
    }
}

// ---------------------------------------------------------------------------
// 4) fill CSR: bucket edges by col, record (src, norm)
// ---------------------------------------------------------------------------
__global__ void fill_kernel(const int* __restrict__ row, const int* __restrict__ col) {
    int e = blockIdx.x * blockDim.x + threadIdx.x;
    if (e >= NE) return;
    int r = __ldg(&row[e]);
    int c = __ldg(&col[e]);
    float nrm = g_deg[r] * g_deg[c];            // g_deg holds dinv here
    int pos = atomicAdd(&g_cur[c], 1);
    g_csr[pos] = make_int2(r, __float_as_int(nrm));
}

// ---------------------------------------------------------------------------
// 5a) split x -> bf16 hi/lo
// ---------------------------------------------------------------------------
__global__ void split_x_kernel(const float* __restrict__ x) {
    size_t i = (size_t)blockIdx.x * blockDim.x + threadIdx.x;
    if (i >= (size_t)NN * NFEAT / 4) return;
    float4 v = reinterpret_cast<const float4*>(x)[i];
    float f[4] = {v.x, v.y, v.z, v.w};
    __nv_bfloat16 hi[4], lo[4];
#pragma unroll
    for (int j = 0; j < 4; j++) {
        hi[j] = __float2bfloat16_rn(f[j]);
        lo[j] = __float2bfloat16_rn(f[j] - __bfloat162float(hi[j]));
    }
    __nv_bfloat162* ph = reinterpret_cast<__nv_bfloat162*>(g_xhi) + i * 2;
    __nv_bfloat162* pl = reinterpret_cast<__nv_bfloat162*>(g_xlo) + i * 2;
    ph[0] = __halves2bfloat162(hi[0], hi[1]);
    ph[1] = __halves2bfloat162(hi[2], hi[3]);
    pl[0] = __halves2bfloat162(lo[0], lo[1]);
    pl[1] = __halves2bfloat162(lo[2], lo[3]);
}

// 5b) split + transpose W1 [512,256] -> W1^T hi/lo [256,512]
__global__ void split_w1_kernel(const float* __restrict__ W1) {
    int i = blockIdx.x * blockDim.x + threadIdx.x;
    if (i >= NHID * NFEAT) return;
    int n = i >> 9;        // /NFEAT
    int k = i & (NFEAT - 1);
    float f = W1[k * NHID + n];
    __nv_bfloat16 hi = __float2bfloat16_rn(f);
    __nv_bfloat16 lo = __float2bfloat16_rn(f - __bfloat162float(hi));
    g_w1hi[i] = hi;
    g_w1lo[i] = lo;
}

// ---------------------------------------------------------------------------
// 5c) GEMM1 tensor-core: h1 = relu(x @ W1 + b1), bf16x3 split, fp32 accum
//     CTA tile 128x256, 8 warps (2x4), warp tile 64x64, BK=32, cp.async x2
// ---------------------------------------------------------------------------
#define T_BM   128
#define T_BK   32
#define T_STR  40                 // padded bf16 row stride (conflict-free)
#define ST_A   (T_BM * T_STR)     // 5120 elems per A buffer
#define ST_B   (NHID * T_STR)     // 10240 elems per B buffer
#define ST_STAGE (2 * ST_A + 2 * ST_B)   // 30720 elems = 61440 B

__global__ void __launch_bounds__(256, 1) gemm1_tc_kernel(const float* __restrict__ b1)
{
    extern __shared__ __nv_bfloat16 smem[];
    const uint32_t sbase = smem_u32(smem);
    const int tid  = threadIdx.x;
    const int wid  = tid >> 5, lane = tid & 31;
    const int wm   = wid >> 2, wn = wid & 3;   // 2 x 4 warp grid
    const int grp  = lane >> 2, qp = lane & 3;
    const int rowBase = blockIdx.x * T_BM;

    float acc[4][8][4];
#pragma unroll
    for (int a = 0; a < 4; a++)
#pragma unroll
        for (int b = 0; b < 8; b++)
#pragma unroll
            for (int c = 0; c < 4; c++) acc[a][b][c] = 0.f;

    // ---- async slab loader ----
    auto load_slab = [&](int ks, int st) {
        uint32_t sb = sbase + st * (ST_STAGE * 2);   // byte base of stage
        // A hi/lo: 512 x 16B chunks each
#pragma unroll
        for (int it = 0; it < 2; it++) {
            int q = tid + it * 256;
            int r = q >> 2, c = q & 3;
            int gr = rowBase + r; if (gr >= NN) gr = NN - 1;
            size_t go = (size_t)gr * NFEAT + ks * T_BK + c * 8;
            cpa16(sb + (r * T_STR + c * 8) * 2,          g_xhi + go);
            cpa16(sb + (ST_A + r * T_STR + c * 8) * 2,   g_xlo + go);
        }
        // B hi/lo: 1024 x 16B chunks each
#pragma unroll
        for (int it = 0; it < 4; it++) {
            int q = tid + it * 256;
            int n = q >> 2, c = q & 3;
            size_t go = (size_t)n * NFEAT + ks * T_BK + c * 8;
            cpa16(sb + (2 * ST_A + n * T_STR + c * 8) * 2,        g_w1hi + go);
            cpa16(sb + (2 * ST_A + ST_B + n * T_STR + c * 8) * 2, g_w1lo + go);
        }
        asm volatile("cp.async.commit_group;");
    };

    // ---- slab compute ----
    auto compute_slab = [&](int st) {
        const __nv_bfloat16* s   = smem + st * ST_STAGE;
        const __nv_bfloat16* sAh = s;
        const __nv_bfloat16* sAl = s + ST_A;
        const __nv_bfloat16* sBh = s + 2 * ST_A;
        const __nv_bfloat16* sBl = s + 2 * ST_A + ST_B;
#pragma unroll
        for (int kstep = 0; kstep < 2; kstep++) {
            const int kk = kstep * 16 + 2 * qp;
            uint32_t ah[4][4], al[4][4];
#pragma unroll
            for (int mt = 0; mt < 4; mt++) {
                int r = wm * 64 + mt * 16 + grp;
                ah[mt][0] = *(const uint32_t*)&sAh[r * T_STR + kk];
                ah[mt][1] = *(const uint32_t*)&sAh[(r + 8) * T_STR + kk];
                ah[mt][2] = *(const uint32_t*)&sAh[r * T_STR + kk + 8];
                ah[mt][3] = *(const uint32_t*)&sAh[(r + 8) * T_STR + kk + 8];
                al[mt][0] = *(const uint32_t*)&sAl[r * T_STR + kk];
                al[mt][1] = *(const uint32_t*)&sAl[(r + 8) * T_STR + kk];
                al[mt][2] = *(const uint32_t*)&sAl[r * T_STR + kk + 8];
                al[mt][3] = *(const uint32_t*)&sAl[(r + 8) * T_STR + kk + 8];
            }
#pragma unroll
            for (int nt = 0; nt < 8; nt++) {
                int n = wn * 64 + nt * 8 + grp;
                uint32_t bh[2], bl[2];
                bh[0] = *(const uint32_t*)&sBh[n * T_STR + kk];
                bh[1] = *(const uint32_t*)&sBh[n * T_STR + kk + 8];
                bl[0] = *(const uint32_t*)&sBl[n * T_STR + kk];
                bl[1] = *(const uint32_t*)&sBl[n * T_STR + kk + 8];
#pragma unroll
                for (int mt = 0; mt < 4; mt++) {
                    mma_bf16(acc[mt][nt], ah[mt], bh);   // hi*hi
                    mma_bf16(acc[mt][nt], ah[mt], bl);   // hi*lo
                    mma_bf16(acc[mt][nt], al[mt], bh);   // lo*hi
                }
            }
        }
    };

    // ---- pipelined mainloop over 16 K-slabs ----
    load_slab(0, 0);
    asm volatile("cp.async.wait_group 0;");
    __syncthreads();
    for (int ks = 0; ks < 16; ks++) {
        int st = ks & 1;
        if (ks < 15) load_slab(ks + 1, st ^ 1);
        compute_slab(st);
        if (ks < 15) {
            asm volatile("cp.async.wait_group 0;");
            __syncthreads();
        }
    }

    // ---- epilogue: bias + relu -> g_h1 ----
#pragma unroll
    for (int mt = 0; mt < 4; mt++) {
        int r0 = rowBase + wm * 64 + mt * 16 + grp;
#pragma unroll
        for (int nt = 0; nt < 8; nt++) {
            int col = wn * 64 + nt * 8 + 2 * qp;
            float bx = __ldg(&b1[col]), by = __ldg(&b1[col + 1]);
            if (r0 < NN) {
                float2 o;
                o.x = fmaxf(acc[mt][nt][0] + bx, 0.f);
                o.y = fmaxf(acc[mt][nt][1] + by, 0.f);
                *reinterpret_cast<float2*>(&g_h1[(size_t)r0 * NHID + col]) = o;
            }
            if (r0 + 8 < NN) {
                float2 o;
                o.x = fmaxf(acc[mt][nt][2] + bx, 0.f);
                o.y = fmaxf(acc[mt][nt][3] + by, 0.f);
                *reinterpret_cast<float2*>(&g_h1[(size_t)(r0 + 8) * NHID + col]) = o;
            }
        }
    }
}

// ---------------------------------------------------------------------------
// 6) GEMM2: h0 = h1 @ W2 + b2 -> g_hA; also out = gamma[0]*h0
// ---------------------------------------------------------------------------
__global__ void gemm2_kernel(const float* __restrict__ W2, const float* __restrict__ b2,
                             const float* __restrict__ gamma, float* __restrict__ out)
{
    __shared__ float4 w2s[NHID * 4];
    const int tid = threadIdx.x;
#pragma unroll
    for (int i = 0; i < 4; i++) {
        int j = tid + i * 256;
        w2s[j] = reinterpret_cast<const float4*>(W2)[j];
    }
    __syncthreads();

    const int row = blockIdx.x * 256 + tid;
    if (row >= NN) return;

    float4 acc[4];
#pragma unroll
    for (int g = 0; g < 4; g++) acc[g] = reinterpret_cast<const float4*>(b2)[g];

    const float4* hr = reinterpret_cast<const float4*>(g_h1 + (size_t)row * NHID);
#pragma unroll 8
    for (int k4 = 0; k4 < NHID / 4; k4++) {
        float4 v = hr[k4];
        float s[4] = {v.x, v.y, v.z, v.w};
#pragma unroll
        for (int u = 0; u < 4; u++) {
#pragma unroll
            for (int g = 0; g < 4; g++) {
                float4 w = w2s[(k4 * 4 + u) * 4 + g];
                acc[g].x += s[u] * w.x;
                acc[g].y += s[u] * w.y;
                acc[g].z += s[u] * w.z;
                acc[g].w += s[u] * w.w;
            }
        }
    }

    float g0 = __ldg(&gamma[0]);
    float4* ha = reinterpret_cast<float4*>(g_hA) + row * 4;
    float4* op = reinterpret_cast<float4*>(out) + row * 4;
#pragma unroll
    for (int g = 0; g < 4; g++) {
        ha[g] = acc[g];
        float4 o;
        o.x = g0 * acc[g].x; o.y = g0 * acc[g].y;
        o.z = g0 * acc[g].z; o.w = g0 * acc[g].w;
        op[g] = o;
    }
}

// ---------------------------------------------------------------------------
// 7) gather sweep: 4 threads per node, one float4 chunk each.
// ---------------------------------------------------------------------------
__global__ void __launch_bounds__(256) gather_kernel(
    float* __restrict__ out, const float* __restrict__ gamma, int k, int flip)
{
    int t = blockIdx.x * blockDim.x + threadIdx.x;
    if (t >= NN * 4) return;
    int n = t >> 2;
    int c = t & 3;

    const float4* src = reinterpret_cast<const float4*>(flip ? g_hB : g_hA);
    float4*       dst = reinterpret_cast<float4*>(flip ? g_hA : g_hB);

    int e0 = __ldg(&g_off[n]);
    int e1 = __ldg(&g_off[n + 1]);

    float4 acc = make_float4(0.f, 0.f, 0.f, 0.f);
#pragma unroll 4
    for (int e = e0; e < e1; e++) {
        int2 er = __ldg(&g_csr[e]);
        float w = __int_as_float(er.y);
        float4 v = __ldg(&src[er.x * 4 + c]);
        acc.x += w * v.x;
        acc.y += w * v.y;
        acc.z += w * v.z;
        acc.w += w * v.w;
    }
    dst[n * 4 + c] = acc;

    float g = __ldg(&gamma[k]);
    float4* op = reinterpret_cast<float4*>(out) + n * 4 + c;
    float4 o = *op;
    o.x += g * acc.x; o.y += g * acc.y;
    o.z += g * acc.z; o.w += g * acc.w;
    *op = o;
}

// ---------------------------------------------------------------------------
// Launch
// ---------------------------------------------------------------------------
extern "C" void kernel_launch(void* const* d_in, const int* in_sizes, int n_in,
                              void* d_out, int out_size)
{
    const float* x     = (const float*)d_in[0];
    const int*   ei    = (const int*)  d_in[1];
    const float* W1    = (const float*)d_in[2];
    const float* b1    = (const float*)d_in[3];
    const float* W2    = (const float*)d_in[4];
    const float* b2    = (const float*)d_in[5];
    const float* gamma = (const float*)d_in[6];
    float*       out   = (float*)d_out;

    const int* row = ei;         // edge_index[0]
    const int* col = ei + NE;    // edge_index[1]

    const int TPB = 256;
    const int ZB  = (NN / 4 + TPB - 1) / TPB;
    const int EB  = (NE + TPB - 1) / TPB;        // 12500
    const int NB  = (NN + TPB - 1) / TPB;        // 391
    const int GB  = (NN * 4 + TPB - 1) / TPB;    // 1563
    const int SXB = ((NN * NFEAT / 4) + TPB - 1) / TPB;
    const int SWB = ((NHID * NFEAT) + TPB - 1) / TPB;
    const int G1B = (NN + T_BM - 1) / T_BM;      // 782

    cudaFuncSetAttribute(gemm1_tc_kernel,
                         cudaFuncAttributeMaxDynamicSharedMemorySize,
                         ST_STAGE * 2 * 2);      // 122880 bytes

    zero_scratch_kernel<<<ZB, TPB>>>();
    count_kernel<<<EB, TPB>>>(row, col);
    dinv_kernel<<<NB, TPB>>>();
    scanA_kernel<<<CB, TPB>>>();
    scanB_kernel<<<1, 512>>>();
    scanC_kernel<<<CB, TPB>>>();
    fill_kernel<<<EB, TPB>>>(row, col);

    split_x_kernel<<<SXB, TPB>>>(x);
    split_w1_kernel<<<SWB, TPB>>>(W1);
    gemm1_tc_kernel<<<G1B, TPB, ST_STAGE * 2 * 2>>>(b1);

    gemm2_kernel<<<NB, TPB>>>(W2, b2, gamma, out);

    for (int k = 1; k <= KHOPS; k++) {
        int flip = (k - 1) & 1;
        gather_kernel<<<GB, TPB>>>(out, gamma, k, flip);
    }
}